// round 4
// baseline (speedup 1.0000x reference)
#include <cuda_runtime.h>
#include <cstdint>

// Chamfer distance, batch=1, P1=P2=16384, D=3, threshold d2>=2 -> 0,
// result = mean(minX)/1 + mean(minY)/1  (scalar float).

#define NPTS   16384
#define BLOCK  512
#define IPT    4                  // queries per thread
#define QPB    (BLOCK * IPT)      // 2048 queries per block
#define NQB    (NPTS / QPB)       // 8 query blocks per direction
#define NSPLIT 37                 // candidate-axis splits -> 2*8*37 = 592 CTAs = 4x148
#define CHUNK  443                // ceil(16384/37); 37*443 = 16391 >= 16384
#define CPAD   444                // even-padded for f32x2 pairs

__device__ int g_min[2 * NPTS];   // per-query running min (float bits, all values >= 0)

__global__ void k_init() {
    int i = blockIdx.x * blockDim.x + threadIdx.x;
    if (i < 2 * NPTS) g_min[i] = 0x7F800000;  // +inf
}

__device__ __forceinline__ unsigned long long pack2(float lo, float hi) {
    unsigned long long r;
    asm("mov.b64 %0, {%1, %2};" : "=l"(r) : "f"(lo), "f"(hi));
    return r;
}
__device__ __forceinline__ void unpack2(unsigned long long v, float& lo, float& hi) {
    asm("mov.b64 {%0, %1}, %2;" : "=f"(lo), "=f"(hi) : "l"(v));
}
// packed dual fp32 FMA (Blackwell f32x2 path; ptxas never auto-fuses this)
__device__ __forceinline__ unsigned long long fma2(unsigned long long a,
                                                   unsigned long long b,
                                                   unsigned long long c) {
    unsigned long long r;
    asm("fma.rn.f32x2 %0, %1, %2, %3;" : "=l"(r) : "l"(a), "l"(b), "l"(c));
    return r;
}

__global__ __launch_bounds__(BLOCK, 2)
void k_chamfer(const float* __restrict__ pc1, const float* __restrict__ pc2) {
    // SoA candidate tile (pair-packed LDS.64 friendly), plus precomputed |y|^2
    __shared__ __align__(16) float sy0[CPAD], sy1[CPAD], sy2[CPAD], syn[CPAD];

    const int dir  = blockIdx.z;                  // 0: pc1->pc2, 1: pc2->pc1
    const float* __restrict__ qp = dir ? pc2 : pc1;
    const float* __restrict__ cp = dir ? pc1 : pc2;
    const int tid   = threadIdx.x;
    const int cbase = blockIdx.x * CHUNK;

    // stage candidate slice: coords + norm; pad with huge norm (never wins the min)
    if (tid < CPAD) {
        int j = cbase + tid;
        float y0 = 0.f, y1 = 0.f, y2 = 0.f, yn = 3.0e38f;
        if (tid < CHUNK && j < NPTS) {
            y0 = cp[3 * j + 0];
            y1 = cp[3 * j + 1];
            y2 = cp[3 * j + 2];
            yn = y0 * y0 + y1 * y1 + y2 * y2;
        }
        sy0[tid] = y0; sy1[tid] = y1; sy2[tid] = y2; syn[tid] = yn;
    }

    // per-thread queries: pre-scale coords by -2 and duplicate into f32x2 operands
    unsigned long long A0[IPT], A1[IPT], A2[IPT];
    float qn[IPT];
    const int qbase = blockIdx.y * QPB + tid;
#pragma unroll
    for (int k = 0; k < IPT; k++) {
        int qi = qbase + k * BLOCK;
        float x0 = qp[3 * qi + 0], x1 = qp[3 * qi + 1], x2 = qp[3 * qi + 2];
        qn[k] = x0 * x0 + x1 * x1 + x2 * x2;
        float a0 = -2.f * x0, a1 = -2.f * x1, a2 = -2.f * x2;
        A0[k] = pack2(a0, a0);
        A1[k] = pack2(a1, a1);
        A2[k] = pack2(a2, a2);
    }
    __syncthreads();

    float m0[IPT], m1[IPT];
#pragma unroll
    for (int k = 0; k < IPT; k++) { m0[k] = 3.0e38f; m1[k] = 3.0e38f; }

    // mainloop: e_j = yn_j - 2*x.y_j, two candidates per packed FMA chain
#pragma unroll 4
    for (int j = 0; j < CPAD; j += 2) {
        unsigned long long Y0 = *(const unsigned long long*)(sy0 + j);
        unsigned long long Y1 = *(const unsigned long long*)(sy1 + j);
        unsigned long long Y2 = *(const unsigned long long*)(sy2 + j);
        unsigned long long YN = *(const unsigned long long*)(syn + j);
#pragma unroll
        for (int k = 0; k < IPT; k++) {
            unsigned long long t = fma2(A0[k], Y0, YN);   // yn - 2x0*y0
            t = fma2(A1[k], Y1, t);
            t = fma2(A2[k], Y2, t);
            float lo, hi;
            unpack2(t, lo, hi);
            m0[k] = fminf(m0[k], lo);                     // FMNMX on alu pipe
            m1[k] = fminf(m1[k], hi);
        }
    }

    // d2 = |x|^2 + min_e ; clamp tiny fp negatives so int-min ordering is valid
#pragma unroll
    for (int k = 0; k < IPT; k++) {
        float d = qn[k] + fminf(m0[k], m1[k]);
        d = fmaxf(d, 0.0f);
        atomicMin(&g_min[dir * NPTS + qbase + k * BLOCK], __float_as_int(d));
    }
}

__global__ void k_reduce(float* __restrict__ out) {
    __shared__ float ss[1024];
    int tid = threadIdx.x;
    float acc = 0.f;
    for (int i = tid; i < 2 * NPTS; i += 1024) {
        float d = __int_as_float(g_min[i]);
        if (d < 2.0f) acc += d;       // threshold: d2 >= 2 contributes 0
    }
    ss[tid] = acc;
    __syncthreads();
    for (int s = 512; s > 0; s >>= 1) {
        if (tid < s) ss[tid] += ss[tid + s];
        __syncthreads();
    }
    // (sumX + sumY) / 16384, since P1 = P2 = 16384 and N = 1
    if (tid == 0) out[0] = ss[0] * (1.0f / (float)NPTS);
}

extern "C" void kernel_launch(void* const* d_in, const int* in_sizes, int n_in,
                              void* d_out, int out_size) {
    const float* pc1 = (const float*)d_in[0];
    const float* pc2 = (const float*)d_in[1];
    (void)in_sizes; (void)n_in; (void)out_size;

    k_init<<<(2 * NPTS + 511) / 512, 512>>>();
    k_chamfer<<<dim3(NSPLIT, NQB, 2), BLOCK>>>(pc1, pc2);
    k_reduce<<<1, 1024>>>((float*)d_out);
}